// round 1
// baseline (speedup 1.0000x reference)
#include <cuda_runtime.h>
#include <cuda_bf16.h>
#include <cstdint>

// Problem constants
#define NTOK 8192
#define DD   128
#define HH   16
#define DH   2048   // DD*HH

// ---------------------------------------------------------------------------
// Device scratch (no cudaMalloc allowed): Qp/Kp/Vp projections and O = attention
// output rows, each [NTOK, DH] fp32.  4 * 64MB = 256MB, allocated at module load.
// ---------------------------------------------------------------------------
__device__ float g_Qp[(size_t)NTOK * DH];
__device__ float g_Kp[(size_t)NTOK * DH];
__device__ float g_Vp[(size_t)NTOK * DH];
__device__ float g_O [(size_t)NTOK * DH];

// ---------------------------------------------------------------------------
// Generic tiled SGEMM with bias:  C[M,Ncols] = A[M,K] @ B[K,Ncols] + bias
// Row-major everywhere.  M % BM == 0, Ncols % BN == 0, K % BK == 0 assumed.
// THREADS = (BM/TM)*(BN/TN) must be 256.
// ---------------------------------------------------------------------------
template<int BM, int BN, int BK, int TM, int TN>
__global__ void __launch_bounds__(256, 2)
sgemm_bias_kernel(const float* __restrict__ A,
                  const float* __restrict__ B,
                  const float* __restrict__ bias,
                  float* __restrict__ C,
                  int M, int Ncols, int K)
{
    constexpr int THREADS = (BM / TM) * (BN / TN);
    static_assert(THREADS == 256, "tile config must give 256 threads");
    constexpr int APAD = 4;

    __shared__ float As[BK * (BM + APAD)];   // transposed: As[k][m]
    __shared__ float Bs[BK * BN];            // Bs[k][n]

    const int tid = threadIdx.x;
    const int bx  = blockIdx.x;
    const int by  = blockIdx.y;
    const int tx  = tid % (BN / TN);
    const int ty  = tid / (BN / TN);

    float acc[TM][TN];
    #pragma unroll
    for (int i = 0; i < TM; i++)
        #pragma unroll
        for (int j = 0; j < TN; j++) acc[i][j] = 0.f;

    // global-load index precompute
    constexpr int A4_PER_THREAD = (BM * BK / 4) / THREADS;  // float4 loads of A per thread
    constexpr int B4_PER_THREAD = (BK * BN / 4) / THREADS;

    for (int k0 = 0; k0 < K; k0 += BK) {
        // ---- load A tile (BM x BK) into As transposed [BK][BM+APAD] ----
        #pragma unroll
        for (int r = 0; r < A4_PER_THREAD; r++) {
            int id  = r * THREADS + tid;          // float4 id within tile
            int row = id / (BK / 4);              // 0..BM-1
            int c4  = (id % (BK / 4)) * 4;        // 0,4,8,12
            float4 va = *(const float4*)(A + (size_t)(by * BM + row) * K + k0 + c4);
            As[(c4 + 0) * (BM + APAD) + row] = va.x;
            As[(c4 + 1) * (BM + APAD) + row] = va.y;
            As[(c4 + 2) * (BM + APAD) + row] = va.z;
            As[(c4 + 3) * (BM + APAD) + row] = va.w;
        }
        // ---- load B tile (BK x BN) into Bs ----
        #pragma unroll
        for (int r = 0; r < B4_PER_THREAD; r++) {
            int id  = r * THREADS + tid;
            int row = id / (BN / 4);              // 0..BK-1
            int c4  = (id % (BN / 4)) * 4;
            *(float4*)&Bs[row * BN + c4] =
                *(const float4*)(B + (size_t)(k0 + row) * Ncols + bx * BN + c4);
        }
        __syncthreads();

        // ---- compute ----
        #pragma unroll
        for (int k = 0; k < BK; k++) {
            float a[TM], b[TN];
            #pragma unroll
            for (int u = 0; u < TM; u += 4)
                *(float4*)(a + u) = *(const float4*)(&As[k * (BM + APAD) + ty * TM + u]);
            #pragma unroll
            for (int u = 0; u < TN; u += 4)
                *(float4*)(b + u) = *(const float4*)(&Bs[k * BN + tx * TN + u]);
            #pragma unroll
            for (int i = 0; i < TM; i++)
                #pragma unroll
                for (int j = 0; j < TN; j++)
                    acc[i][j] += a[i] * b[j];
        }
        __syncthreads();
    }

    // ---- epilogue: add bias, write ----
    #pragma unroll
    for (int i = 0; i < TM; i++) {
        int row = by * BM + ty * TM + i;
        #pragma unroll
        for (int j = 0; j < TN; j += 4) {
            int col = bx * BN + tx * TN + j;
            float4 bv = *(const float4*)(bias + col);
            float4 o;
            o.x = acc[i][j + 0] + bv.x;
            o.y = acc[i][j + 1] + bv.y;
            o.z = acc[i][j + 2] + bv.z;
            o.w = acc[i][j + 3] + bv.w;
            *(float4*)(C + (size_t)row * Ncols + col) = o;
        }
    }
}

// ---------------------------------------------------------------------------
// Per-token attention.  One block per token, 256 threads.
//   Q3[i][h] = Qp[n][i*16+h]  (same for K3, V3)
//   S[i][j]  = (1/sqrt(128)) * sum_h Q3[i][h] * K3[j][h]
//   attn     = softmax over i (per column j)
//   out3[i][h] = sum_j attn[i][j] * V3[j][h]
//   O[n][i*16+h] = out3[i][h]   (flattened row-major, free reshape)
// ---------------------------------------------------------------------------
#define SV_LD  17     // sV row stride (pad)
#define SS_LD  129    // sS row stride (pad)

__global__ void __launch_bounds__(256, 2)
attention_kernel(const float* __restrict__ Qp,
                 const float* __restrict__ Kp,
                 const float* __restrict__ Vp,
                 float* __restrict__ O)
{
    extern __shared__ float sm[];
    float* sQ = sm;                    // [16][128]  sQ[h*128 + i]
    float* sK = sQ + 16 * DD;          // [16][128]
    float* sV = sK + 16 * DD;          // [128][17]  sV[j*17 + h]
    float* sS = sV + DD * SV_LD;       // [128][129] sS[i*129 + j]

    const int n   = blockIdx.x;
    const int tid = threadIdx.x;

    const float* qrow = Qp + (size_t)n * DH;
    const float* krow = Kp + (size_t)n * DH;
    const float* vrow = Vp + (size_t)n * DH;

    // ---- load + transpose into smem: 512 float4 per tensor, 2 per thread ----
    #pragma unroll
    for (int r = 0; r < 2; r++) {
        int f4 = r * 256 + tid;
        int f  = f4 * 4;
        int i  = f / HH;           // token-feature row
        int h  = f % HH;           // 0,4,8,12
        float4 q4 = *(const float4*)(qrow + f);
        float4 k4 = *(const float4*)(krow + f);
        float4 v4 = *(const float4*)(vrow + f);
        sQ[(h + 0) * DD + i] = q4.x;  sQ[(h + 1) * DD + i] = q4.y;
        sQ[(h + 2) * DD + i] = q4.z;  sQ[(h + 3) * DD + i] = q4.w;
        sK[(h + 0) * DD + i] = k4.x;  sK[(h + 1) * DD + i] = k4.y;
        sK[(h + 2) * DD + i] = k4.z;  sK[(h + 3) * DD + i] = k4.w;
        sV[i * SV_LD + h + 0] = v4.x; sV[i * SV_LD + h + 1] = v4.y;
        sV[i * SV_LD + h + 2] = v4.z; sV[i * SV_LD + h + 3] = v4.w;
    }
    __syncthreads();

    // ---- scores: 128x128x16 GEMM, 8x8 per thread ----
    {
        const int tx = tid % 16;
        const int ty = tid / 16;
        float acc[8][8];
        #pragma unroll
        for (int i = 0; i < 8; i++)
            #pragma unroll
            for (int j = 0; j < 8; j++) acc[i][j] = 0.f;

        #pragma unroll
        for (int h = 0; h < 16; h++) {
            float a[8], b[8];
            *(float4*)(a)     = *(const float4*)(sQ + h * DD + ty * 8);
            *(float4*)(a + 4) = *(const float4*)(sQ + h * DD + ty * 8 + 4);
            *(float4*)(b)     = *(const float4*)(sK + h * DD + tx * 8);
            *(float4*)(b + 4) = *(const float4*)(sK + h * DD + tx * 8 + 4);
            #pragma unroll
            for (int i = 0; i < 8; i++)
                #pragma unroll
                for (int j = 0; j < 8; j++)
                    acc[i][j] += a[i] * b[j];
        }
        const float scale = 0.08838834764831845f;  // 1/sqrt(128)
        #pragma unroll
        for (int i = 0; i < 8; i++)
            #pragma unroll
            for (int j = 0; j < 8; j++)
                sS[(ty * 8 + i) * SS_LD + (tx * 8 + j)] = acc[i][j] * scale;
    }
    __syncthreads();

    // ---- softmax over i, per column j (threads 0..127, one column each) ----
    if (tid < DD) {
        const int j = tid;
        float m = -1e30f;
        #pragma unroll 4
        for (int i = 0; i < DD; i++) m = fmaxf(m, sS[i * SS_LD + j]);
        float s0 = 0.f, s1 = 0.f, s2 = 0.f, s3 = 0.f;
        for (int i = 0; i < DD; i += 4) {
            float e0 = __expf(sS[(i + 0) * SS_LD + j] - m);
            float e1 = __expf(sS[(i + 1) * SS_LD + j] - m);
            float e2 = __expf(sS[(i + 2) * SS_LD + j] - m);
            float e3 = __expf(sS[(i + 3) * SS_LD + j] - m);
            sS[(i + 0) * SS_LD + j] = e0;  s0 += e0;
            sS[(i + 1) * SS_LD + j] = e1;  s1 += e1;
            sS[(i + 2) * SS_LD + j] = e2;  s2 += e2;
            sS[(i + 3) * SS_LD + j] = e3;  s3 += e3;
        }
        float inv = 1.f / (s0 + s1 + s2 + s3);
        #pragma unroll 4
        for (int i = 0; i < DD; i++) sS[i * SS_LD + j] *= inv;
    }
    __syncthreads();

    // ---- out3[i][h] = sum_j attn[i][j] * sV[j][h] ; thread does 4 i x 2 h ----
    {
        const int tg = tid >> 3;      // 0..31 -> i base tg*4
        const int th = tid & 7;       // 0..7  -> h pair {2th, 2th+1}
        float o[4][2];
        #pragma unroll
        for (int ii = 0; ii < 4; ii++) { o[ii][0] = 0.f; o[ii][1] = 0.f; }

        for (int j = 0; j < DD; j++) {
            float v0 = sV[j * SV_LD + 2 * th];
            float v1 = sV[j * SV_LD + 2 * th + 1];
            #pragma unroll
            for (int ii = 0; ii < 4; ii++) {
                float a = sS[(tg * 4 + ii) * SS_LD + j];
                o[ii][0] += a * v0;
                o[ii][1] += a * v1;
            }
        }
        float* orow = O + (size_t)n * DH;
        #pragma unroll
        for (int ii = 0; ii < 4; ii++) {
            int i = tg * 4 + ii;
            *(float2*)(orow + i * HH + 2 * th) = make_float2(o[ii][0], o[ii][1]);
        }
    }
}

// ---------------------------------------------------------------------------
// Launcher
// ---------------------------------------------------------------------------
#define ATT_SMEM_FLOATS (16*DD + 16*DD + DD*SV_LD + DD*SS_LD)
#define ATT_SMEM_BYTES  (ATT_SMEM_FLOATS * 4)

extern "C" void kernel_launch(void* const* d_in, const int* in_sizes, int n_in,
                              void* d_out, int out_size)
{
    const float* q  = (const float*)d_in[0];
    const float* k  = (const float*)d_in[1];
    const float* v  = (const float*)d_in[2];
    const float* Wq = (const float*)d_in[3];
    const float* bq = (const float*)d_in[4];
    const float* Wk = (const float*)d_in[5];
    const float* bk = (const float*)d_in[6];
    const float* Wv = (const float*)d_in[7];
    const float* bv = (const float*)d_in[8];
    const float* Wo = (const float*)d_in[9];
    const float* bo = (const float*)d_in[10];
    float* out = (float*)d_out;
    (void)in_sizes; (void)n_in; (void)out_size;

    float *Qp = nullptr, *Kp = nullptr, *Vp = nullptr, *Og = nullptr;
    cudaGetSymbolAddress((void**)&Qp, g_Qp);
    cudaGetSymbolAddress((void**)&Kp, g_Kp);
    cudaGetSymbolAddress((void**)&Vp, g_Vp);
    cudaGetSymbolAddress((void**)&Og, g_O);

    cudaFuncSetAttribute(attention_kernel,
                         cudaFuncAttributeMaxDynamicSharedMemorySize,
                         ATT_SMEM_BYTES);

    // 1) projections: [8192,128] @ [128,2048] + bias
    dim3 gproj(DH / 128, NTOK / 128);
    sgemm_bias_kernel<128,128,16,8,8><<<gproj, 256>>>(q, Wq, bq, Qp, NTOK, DH, DD);
    sgemm_bias_kernel<128,128,16,8,8><<<gproj, 256>>>(k, Wk, bk, Kp, NTOK, DH, DD);
    sgemm_bias_kernel<128,128,16,8,8><<<gproj, 256>>>(v, Wv, bv, Vp, NTOK, DH, DD);

    // 2) per-token attention
    attention_kernel<<<NTOK, 256, ATT_SMEM_BYTES>>>(Qp, Kp, Vp, Og);

    // 3) output projection: [8192,2048] @ [2048,128] + bias
    dim3 gout(DD / 128, NTOK / 64);
    sgemm_bias_kernel<64,128,16,4,8><<<gout, 256>>>(Og, Wo, bo, out, NTOK, DD, DH);
}

// round 2
// speedup vs baseline: 1.3975x; 1.3975x over previous
#include <cuda_runtime.h>
#include <cuda_bf16.h>
#include <cstdint>

// Problem constants
#define NTOK 8192
#define DD   128
#define HH   16
#define DH   2048   // DD*HH

typedef __nv_bfloat16 bf16;

// ---------------------------------------------------------------------------
// Device scratch (no cudaMalloc allowed).
// ---------------------------------------------------------------------------
__device__ float g_Qp[(size_t)NTOK * DH];      // fp32 projections (attention input)
__device__ float g_Kp[(size_t)NTOK * DH];
__device__ float g_Vp[(size_t)NTOK * DH];

__device__ bf16  g_Aq[(size_t)NTOK * 3 * DD];  // packed [hi|lo|hi] inputs, K=384
__device__ bf16  g_Ak[(size_t)NTOK * 3 * DD];
__device__ bf16  g_Av[(size_t)NTOK * 3 * DD];
__device__ bf16  g_Bq[(size_t)3 * DD * DH];    // packed [hi;hi;lo] weights
__device__ bf16  g_Bk[(size_t)3 * DD * DH];
__device__ bf16  g_Bv[(size_t)3 * DD * DH];
__device__ bf16  g_Bo[(size_t)3 * DH * DD];    // Wo packed, K2=6144, N=128
__device__ bf16  g_Obf[(size_t)NTOK * 3 * DH]; // attention out, packed hi|lo|hi

// ---------------------------------------------------------------------------
// PTX helpers
// ---------------------------------------------------------------------------
__device__ __forceinline__ uint32_t smem_u32(const void* p) {
    return (uint32_t)__cvta_generic_to_shared(p);
}
__device__ __forceinline__ void ldm_x4(uint32_t& r0, uint32_t& r1, uint32_t& r2,
                                       uint32_t& r3, uint32_t addr) {
    asm volatile("ldmatrix.sync.aligned.m8n8.x4.shared.b16 {%0,%1,%2,%3}, [%4];\n"
                 : "=r"(r0), "=r"(r1), "=r"(r2), "=r"(r3) : "r"(addr));
}
__device__ __forceinline__ void ldm_x2_t(uint32_t& r0, uint32_t& r1, uint32_t addr) {
    asm volatile("ldmatrix.sync.aligned.m8n8.x2.trans.shared.b16 {%0,%1}, [%2];\n"
                 : "=r"(r0), "=r"(r1) : "r"(addr));
}
__device__ __forceinline__ void mma_bf16(float c[4], const uint32_t a[4],
                                         const uint32_t b[2]) {
    asm volatile(
        "mma.sync.aligned.m16n8k16.row.col.f32.bf16.bf16.f32 "
        "{%0,%1,%2,%3}, {%4,%5,%6,%7}, {%8,%9}, {%0,%1,%2,%3};\n"
        : "+f"(c[0]), "+f"(c[1]), "+f"(c[2]), "+f"(c[3])
        : "r"(a[0]), "r"(a[1]), "r"(a[2]), "r"(a[3]), "r"(b[0]), "r"(b[1]));
}
__device__ __forceinline__ void cp_async16(void* dst, const void* src) {
    asm volatile("cp.async.cg.shared.global [%0], [%1], 16;\n"
                 :: "r"(smem_u32(dst)), "l"(src));
}
__device__ __forceinline__ void cp_commit() {
    asm volatile("cp.async.commit_group;\n");
}
template<int N>
__device__ __forceinline__ void cp_wait() {
    asm volatile("cp.async.wait_group %0;\n" :: "n"(N));
}

// ---------------------------------------------------------------------------
// Split/pack kernels: fp32 -> bf16 two-term split, K-concatenated.
//   A2 = [hi | lo | hi]  (columns),  B2 = [hi ; hi ; lo]  (rows)
//   => A2 @ B2 = A_hi B_hi + A_lo B_hi + A_hi B_lo  (3xbf16 ~= fp32)
// ---------------------------------------------------------------------------
__global__ void pack_A_kernel(const float* __restrict__ src, bf16* __restrict__ dst,
                              int M, int K) {
    int total = M * K;
    for (int idx = blockIdx.x * blockDim.x + threadIdx.x; idx < total;
         idx += gridDim.x * blockDim.x) {
        int m = idx / K, c = idx % K;
        float v  = src[idx];
        bf16 hi  = __float2bfloat16(v);
        bf16 lo  = __float2bfloat16(v - __bfloat162float(hi));
        size_t r = (size_t)m * 3 * K;
        dst[r + c] = hi; dst[r + K + c] = lo; dst[r + 2 * K + c] = hi;
    }
}
__global__ void pack_B_kernel(const float* __restrict__ src, bf16* __restrict__ dst,
                              int K, int N) {
    int total = K * N;
    for (int idx = blockIdx.x * blockDim.x + threadIdx.x; idx < total;
         idx += gridDim.x * blockDim.x) {
        int k = idx / N, n = idx % N;
        float v = src[idx];
        bf16 hi = __float2bfloat16(v);
        bf16 lo = __float2bfloat16(v - __bfloat162float(hi));
        dst[(size_t)k * N + n]           = hi;
        dst[(size_t)(K + k) * N + n]     = hi;
        dst[(size_t)(2 * K + k) * N + n] = lo;
    }
}

// ---------------------------------------------------------------------------
// bf16 tensor-core GEMM:  C[M,N] = A2[M,K2] @ B2[K2,N] + bias   (fp32 out)
// 256 threads = 8 warps arranged (BM/WM) x (BN/WN).  mma.sync m16n8k16.
// ---------------------------------------------------------------------------
template<int BM, int BN, int BK, int WM, int WN>
__global__ void __launch_bounds__(256, 2)
gemm_bf16_kernel(const bf16* __restrict__ A, const bf16* __restrict__ B,
                 const float* __restrict__ bias, float* __restrict__ C,
                 int M, int N, int K2)
{
    constexpr int WARPS_M = BM / WM, WARPS_N = BN / WN;
    static_assert(WARPS_M * WARPS_N == 8, "8 warps");
    constexpr int MT = WM / 16, NT = WN / 8;
    constexpr int LDA = BK + 8, LDB = BN + 8;   // pad: conflict-free ldmatrix
    constexpr int A_CH = BM * BK / 8 / 256;     // 16B chunks per thread
    constexpr int B_CH = BK * BN / 8 / 256;

    __shared__ __align__(16) bf16 As[2][BM * LDA];
    __shared__ __align__(16) bf16 Bs[2][BK * LDB];

    const int tid  = threadIdx.x;
    const int lane = tid & 31, wid = tid >> 5;
    const int wm   = wid % WARPS_M, wn = wid / WARPS_M;
    const int bx   = blockIdx.x, by = blockIdx.y;

    const bf16* Ag = A + (size_t)(by * BM) * K2;
    const bf16* Bg = B + bx * BN;

    float acc[MT][NT][4];
    #pragma unroll
    for (int i = 0; i < MT; i++)
        #pragma unroll
        for (int j = 0; j < NT; j++)
            #pragma unroll
            for (int u = 0; u < 4; u++) acc[i][j][u] = 0.f;

    const int ntile = K2 / BK;

    auto load_tile = [&](int t, int buf) {
        int k0 = t * BK;
        #pragma unroll
        for (int r = 0; r < A_CH; r++) {
            int id = r * 256 + tid;
            int row = id / (BK / 8), c8 = (id % (BK / 8)) * 8;
            cp_async16(&As[buf][row * LDA + c8], Ag + (size_t)row * K2 + k0 + c8);
        }
        #pragma unroll
        for (int r = 0; r < B_CH; r++) {
            int id = r * 256 + tid;
            int row = id / (BN / 8), c8 = (id % (BN / 8)) * 8;
            cp_async16(&Bs[buf][row * LDB + c8], Bg + (size_t)(k0 + row) * N + c8);
        }
        cp_commit();
    };

    load_tile(0, 0);

    for (int t = 0; t < ntile; t++) {
        int cur = t & 1;
        if (t + 1 < ntile) { load_tile(t + 1, (t + 1) & 1); cp_wait<1>(); }
        else               { cp_wait<0>(); }
        __syncthreads();

        #pragma unroll
        for (int ks = 0; ks < BK / 16; ks++) {
            uint32_t af[MT][4];
            #pragma unroll
            for (int mt = 0; mt < MT; mt++) {
                uint32_t addr = smem_u32(&As[cur][(wm * WM + mt * 16 + (lane & 15)) * LDA
                                                  + ks * 16 + (lane >> 4) * 8]);
                ldm_x4(af[mt][0], af[mt][1], af[mt][2], af[mt][3], addr);
            }
            uint32_t bfr[NT][2];
            #pragma unroll
            for (int nt = 0; nt < NT; nt++) {
                uint32_t addr = smem_u32(&Bs[cur][(ks * 16 + (lane & 15)) * LDB
                                                  + wn * WN + nt * 8]);
                ldm_x2_t(bfr[nt][0], bfr[nt][1], addr);
            }
            #pragma unroll
            for (int mt = 0; mt < MT; mt++)
                #pragma unroll
                for (int nt = 0; nt < NT; nt++)
                    mma_bf16(acc[mt][nt], af[mt], bfr[nt]);
        }
        __syncthreads();
    }

    // epilogue: bias + fp32 store
    const int row0 = by * BM + wm * WM + lane / 4;
    const int col0 = bx * BN + wn * WN + (lane & 3) * 2;
    #pragma unroll
    for (int mt = 0; mt < MT; mt++) {
        #pragma unroll
        for (int nt = 0; nt < NT; nt++) {
            int r = row0 + mt * 16, c = col0 + nt * 8;
            float2 bv = *(const float2*)(bias + c);
            float2 v0 = make_float2(acc[mt][nt][0] + bv.x, acc[mt][nt][1] + bv.y);
            float2 v1 = make_float2(acc[mt][nt][2] + bv.x, acc[mt][nt][3] + bv.y);
            *(float2*)(C + (size_t)r * N + c)       = v0;
            *(float2*)(C + (size_t)(r + 8) * N + c) = v1;
        }
    }
}

// ---------------------------------------------------------------------------
// Per-token attention (unchanged math).  Output written directly in the
// packed [hi|lo|hi] bf16 layout (K2 = 3*DH) for the output GEMM.
// ---------------------------------------------------------------------------
#define SV_LD  17
#define SS_LD  129

__global__ void __launch_bounds__(256, 2)
attention_kernel(const float* __restrict__ Qp,
                 const float* __restrict__ Kp,
                 const float* __restrict__ Vp,
                 bf16* __restrict__ Obf)
{
    extern __shared__ float sm[];
    float* sQ = sm;
    float* sK = sQ + 16 * DD;
    float* sV = sK + 16 * DD;
    float* sS = sV + DD * SV_LD;

    const int n   = blockIdx.x;
    const int tid = threadIdx.x;

    const float* qrow = Qp + (size_t)n * DH;
    const float* krow = Kp + (size_t)n * DH;
    const float* vrow = Vp + (size_t)n * DH;

    #pragma unroll
    for (int r = 0; r < 2; r++) {
        int f4 = r * 256 + tid;
        int f  = f4 * 4;
        int i  = f / HH;
        int h  = f % HH;
        float4 q4 = *(const float4*)(qrow + f);
        float4 k4 = *(const float4*)(krow + f);
        float4 v4 = *(const float4*)(vrow + f);
        sQ[(h + 0) * DD + i] = q4.x;  sQ[(h + 1) * DD + i] = q4.y;
        sQ[(h + 2) * DD + i] = q4.z;  sQ[(h + 3) * DD + i] = q4.w;
        sK[(h + 0) * DD + i] = k4.x;  sK[(h + 1) * DD + i] = k4.y;
        sK[(h + 2) * DD + i] = k4.z;  sK[(h + 3) * DD + i] = k4.w;
        sV[i * SV_LD + h + 0] = v4.x; sV[i * SV_LD + h + 1] = v4.y;
        sV[i * SV_LD + h + 2] = v4.z; sV[i * SV_LD + h + 3] = v4.w;
    }
    __syncthreads();

    {
        const int tx = tid % 16;
        const int ty = tid / 16;
        float acc[8][8];
        #pragma unroll
        for (int i = 0; i < 8; i++)
            #pragma unroll
            for (int j = 0; j < 8; j++) acc[i][j] = 0.f;

        #pragma unroll
        for (int h = 0; h < 16; h++) {
            float a[8], b[8];
            *(float4*)(a)     = *(const float4*)(sQ + h * DD + ty * 8);
            *(float4*)(a + 4) = *(const float4*)(sQ + h * DD + ty * 8 + 4);
            *(float4*)(b)     = *(const float4*)(sK + h * DD + tx * 8);
            *(float4*)(b + 4) = *(const float4*)(sK + h * DD + tx * 8 + 4);
            #pragma unroll
            for (int i = 0; i < 8; i++)
                #pragma unroll
                for (int j = 0; j < 8; j++)
                    acc[i][j] += a[i] * b[j];
        }
        const float scale = 0.08838834764831845f;
        #pragma unroll
        for (int i = 0; i < 8; i++)
            #pragma unroll
            for (int j = 0; j < 8; j++)
                sS[(ty * 8 + i) * SS_LD + (tx * 8 + j)] = acc[i][j] * scale;
    }
    __syncthreads();

    if (tid < DD) {
        const int j = tid;
        float m = -1e30f;
        #pragma unroll 4
        for (int i = 0; i < DD; i++) m = fmaxf(m, sS[i * SS_LD + j]);
        float s0 = 0.f, s1 = 0.f, s2 = 0.f, s3 = 0.f;
        for (int i = 0; i < DD; i += 4) {
            float e0 = __expf(sS[(i + 0) * SS_LD + j] - m);
            float e1 = __expf(sS[(i + 1) * SS_LD + j] - m);
            float e2 = __expf(sS[(i + 2) * SS_LD + j] - m);
            float e3 = __expf(sS[(i + 3) * SS_LD + j] - m);
            sS[(i + 0) * SS_LD + j] = e0;  s0 += e0;
            sS[(i + 1) * SS_LD + j] = e1;  s1 += e1;
            sS[(i + 2) * SS_LD + j] = e2;  s2 += e2;
            sS[(i + 3) * SS_LD + j] = e3;  s3 += e3;
        }
        float inv = 1.f / (s0 + s1 + s2 + s3);
        #pragma unroll 4
        for (int i = 0; i < DD; i++) sS[i * SS_LD + j] *= inv;
    }
    __syncthreads();

    {
        const int tg = tid >> 3;
        const int th = tid & 7;
        float o[4][2];
        #pragma unroll
        for (int ii = 0; ii < 4; ii++) { o[ii][0] = 0.f; o[ii][1] = 0.f; }

        for (int j = 0; j < DD; j++) {
            float v0 = sV[j * SV_LD + 2 * th];
            float v1 = sV[j * SV_LD + 2 * th + 1];
            #pragma unroll
            for (int ii = 0; ii < 4; ii++) {
                float a = sS[(tg * 4 + ii) * SS_LD + j];
                o[ii][0] += a * v0;
                o[ii][1] += a * v1;
            }
        }
        bf16* obase = Obf + (size_t)n * (3 * DH);
        #pragma unroll
        for (int ii = 0; ii < 4; ii++) {
            int i = tg * 4 + ii;
            int f = i * HH + 2 * th;
            float o0 = o[ii][0], o1 = o[ii][1];
            bf16 h0 = __float2bfloat16(o0), h1 = __float2bfloat16(o1);
            bf16 l0 = __float2bfloat16(o0 - __bfloat162float(h0));
            bf16 l1 = __float2bfloat16(o1 - __bfloat162float(h1));
            __nv_bfloat162 hv = __halves2bfloat162(h0, h1);
            __nv_bfloat162 lv = __halves2bfloat162(l0, l1);
            *(__nv_bfloat162*)(obase + f)          = hv;
            *(__nv_bfloat162*)(obase + DH + f)     = lv;
            *(__nv_bfloat162*)(obase + 2 * DH + f) = hv;
        }
    }
}

// ---------------------------------------------------------------------------
// Launcher
// ---------------------------------------------------------------------------
#define ATT_SMEM_FLOATS (16*DD + 16*DD + DD*SV_LD + DD*SS_LD)
#define ATT_SMEM_BYTES  (ATT_SMEM_FLOATS * 4)

extern "C" void kernel_launch(void* const* d_in, const int* in_sizes, int n_in,
                              void* d_out, int out_size)
{
    const float* q  = (const float*)d_in[0];
    const float* k  = (const float*)d_in[1];
    const float* v  = (const float*)d_in[2];
    const float* Wq = (const float*)d_in[3];
    const float* bq = (const float*)d_in[4];
    const float* Wk = (const float*)d_in[5];
    const float* bk = (const float*)d_in[6];
    const float* Wv = (const float*)d_in[7];
    const float* bv = (const float*)d_in[8];
    const float* Wo = (const float*)d_in[9];
    const float* bo = (const float*)d_in[10];
    float* out = (float*)d_out;
    (void)in_sizes; (void)n_in; (void)out_size;

    float *Qp, *Kp, *Vp;
    bf16 *Aq, *Ak, *Av, *Bq, *Bk, *Bv, *Bo, *Obf;
    cudaGetSymbolAddress((void**)&Qp,  g_Qp);
    cudaGetSymbolAddress((void**)&Kp,  g_Kp);
    cudaGetSymbolAddress((void**)&Vp,  g_Vp);
    cudaGetSymbolAddress((void**)&Aq,  g_Aq);
    cudaGetSymbolAddress((void**)&Ak,  g_Ak);
    cudaGetSymbolAddress((void**)&Av,  g_Av);
    cudaGetSymbolAddress((void**)&Bq,  g_Bq);
    cudaGetSymbolAddress((void**)&Bk,  g_Bk);
    cudaGetSymbolAddress((void**)&Bv,  g_Bv);
    cudaGetSymbolAddress((void**)&Bo,  g_Bo);
    cudaGetSymbolAddress((void**)&Obf, g_Obf);

    cudaFuncSetAttribute(attention_kernel,
                         cudaFuncAttributeMaxDynamicSharedMemorySize,
                         ATT_SMEM_BYTES);

    // 0) pack inputs/weights into bf16 split form
    pack_A_kernel<<<256, 256>>>(q, Aq, NTOK, DD);
    pack_A_kernel<<<256, 256>>>(k, Ak, NTOK, DD);
    pack_A_kernel<<<256, 256>>>(v, Av, NTOK, DD);
    pack_B_kernel<<<128, 256>>>(Wq, Bq, DD, DH);
    pack_B_kernel<<<128, 256>>>(Wk, Bk, DD, DH);
    pack_B_kernel<<<128, 256>>>(Wv, Bv, DD, DH);
    pack_B_kernel<<<128, 256>>>(Wo, Bo, DH, DD);

    // 1) projections: [8192,384]bf16 @ [384,2048]bf16 -> fp32
    dim3 gproj(DH / 128, NTOK / 128);
    gemm_bf16_kernel<128,128,32,64,32><<<gproj, 256>>>(Aq, Bq, bq, Qp, NTOK, DH, 3 * DD);
    gemm_bf16_kernel<128,128,32,64,32><<<gproj, 256>>>(Ak, Bk, bk, Kp, NTOK, DH, 3 * DD);
    gemm_bf16_kernel<128,128,32,64,32><<<gproj, 256>>>(Av, Bv, bv, Vp, NTOK, DH, 3 * DD);

    // 2) per-token attention (emits packed bf16 output)
    attention_kernel<<<NTOK, 256, ATT_SMEM_BYTES>>>(Qp, Kp, Vp, Obf);

    // 3) output projection: [8192,6144]bf16 @ [6144,128]bf16 -> fp32
    dim3 gout(DD / 64, NTOK / 64);
    gemm_bf16_kernel<64,64,64,32,16><<<gout, 256>>>(Obf, Bo, bo, out, NTOK, DD, 3 * DH);
}